// round 10
// baseline (speedup 1.0000x reference)
#include <cuda_runtime.h>
#include <math.h>

#define NL 51
#define NC 16
#define PCX 33          // 16 sums + 16 normsums + count
#define NRED (NL * PCX) // 1683
#define GRID1 444       // 3 CTAs/SM * 148
#define BLK1 512
#define TILE 256
#define NT 16384        // 4194304 voxels / 256
#define ROWB 1040       // staged p row stride (bytes): 256*4 + 16
#define CAP 16

static const long long CH_STRIDE = 1LL << 21;   // floats per channel plane

// dynamic smem layout (bytes)
#define P_OFF(b)   ((b) * 16640)                 // 16 rows * 1040
#define GT_OFF(b)  (33280 + (b) * 1024)
#define IDX_OFF    35328                         // ushort[51][16] = 1632 (+pad)
#define BINV_OFF   36992                         // float[51][16] = 3264
#define CUR_OFF    40256                         // int[51] + pad
#define SS_OFF     40464                         // float[51][16]
#define SN_OFF     43728                         // float[51][16]
#define SCNT_OFF   46992                         // float[51]
#define SMEM1      47232

#define CP_ASYNC16(dst, src) \
    asm volatile("cp.async.cg.shared.global [%0], [%1], 16;\n" :: "r"(dst), "l"(src))
#define CP_COMMIT() asm volatile("cp.async.commit_group;\n" ::: "memory")
#define CP_WAIT1()  asm volatile("cp.async.wait_group 1;\n" ::: "memory")
#define CP_WAIT0()  asm volatile("cp.async.wait_group 0;\n" ::: "memory")

// Global reduction target; zero-initialized at load, re-zeroed by k_finish each call
static __device__ double g_red_d[NRED];

__device__ __forceinline__ double blockReduceD(double v) {
    __shared__ double sh[32];
    int lane = threadIdx.x & 31, w = threadIdx.x >> 5;
    #pragma unroll
    for (int o = 16; o; o >>= 1) v += __shfl_down_sync(0xffffffffu, v, o);
    if (lane == 0) sh[w] = v;
    __syncthreads();
    int nw = (blockDim.x + 31) >> 5;
    v = (threadIdx.x < nw) ? sh[threadIdx.x] : 0.0;
    if (w == 0) {
        #pragma unroll
        for (int o = 16; o; o >>= 1) v += __shfl_down_sync(0xffffffffu, v, o);
    }
    return v; // valid on thread 0
}

__device__ __forceinline__ void issue_tile(unsigned sm32, int t, int buf,
                                           const float* __restrict__ pred,
                                           const int* __restrict__ gt) {
    size_t v0 = (size_t)t * TILE;
    const char* psrc = (const char*)(pred + (v0 >> 21) * (NC * (size_t)CH_STRIDE)
                                          + (v0 & (size_t)(CH_STRIDE - 1)));
    int tid = threadIdx.x;
    #pragma unroll
    for (int it = 0; it < 2; it++) {
        int o = tid + it * BLK1;         // 0..1023
        int k = o >> 6, c = o & 63;      // 64 16B-granules per 256-float row
        unsigned dst = sm32 + P_OFF(buf) + k * ROWB + c * 16;
        const char* src = psrc + (size_t)k * ((size_t)CH_STRIDE * 4) + (size_t)c * 16;
        CP_ASYNC16(dst, src);
    }
    if (tid < 64) {
        unsigned dstg = sm32 + GT_OFF(buf) + tid * 16;
        const char* srcg = (const char*)(gt + v0) + (size_t)tid * 16;
        CP_ASYNC16(dstg, srcg);
    }
}

// ---------- Fused pass: per-label count, sum(p), sum(p/|p|) in ONE data read ----------
__global__ void __launch_bounds__(BLK1, 3) k_fused(const float* __restrict__ pred,
                                                   const int* __restrict__ gt) {
    extern __shared__ char sm[];
    float* sS = (float*)(sm + SS_OFF);
    float* sN = (float*)(sm + SN_OFF);
    float* scnt = (float*)(sm + SCNT_OFF);
    int* cursor = (int*)(sm + CUR_OFF);
    unsigned short* sidx = (unsigned short*)(sm + IDX_OFF);
    float* sbinv = (float*)(sm + BINV_OFF);
    const int tid = threadIdx.x;
    const int lane = tid & 31, w = tid >> 5;
    const int k = lane & 15, s = lane >> 4;

    unsigned sm32;
    asm("{ .reg .u64 t; cvta.to.shared.u64 t, %1; cvt.u32.u64 %0, t; }"
        : "=r"(sm32) : "l"(sm));

    for (int i = tid; i < NL * NC; i += BLK1) { sS[i] = 0.f; sN[i] = 0.f; }
    if (tid < NL) scnt[tid] = 0.f;
    __syncthreads();

    issue_tile(sm32, blockIdx.x, 0, pred, gt);
    CP_COMMIT();

    int it = 0;
    for (int t = blockIdx.x; t < NT; t += GRID1, it++) {
        int buf = it & 1;
        int tn = t + GRID1;
        if (tn < NT) {
            issue_tile(sm32, tn, buf ^ 1, pred, gt);
            CP_COMMIT();
            CP_WAIT1();
        } else {
            CP_WAIT0();
        }
        __syncthreads();

        if (tid < NL) cursor[tid] = 0;
        __syncthreads();

        // scatter + norm: thread pair per voxel (h in {0,1} takes 8 channels)
        {
            int v = tid >> 1, h = tid & 1;
            int l = *(const int*)(sm + GT_OFF(buf) + v * 4);
            const char* pb = sm + P_OFF(buf) + h * 8 * ROWB + v * 4;
            float q = 0.f;
            #pragma unroll
            for (int kk = 0; kk < 8; kk++) {
                float pp = *(const float*)(pb + kk * ROWB);
                q += pp * pp;
            }
            q += __shfl_xor_sync(0xffffffffu, q, 1);
            if (h == 0) {
                float inv = rsqrtf(fmaxf(q, 1e-30f));
                int r = atomicAdd(&cursor[l], 1);
                if (r < CAP) {
                    sidx[l * CAP + r] = (unsigned short)v;
                    sbinv[l * CAP + r] = inv;
                } else {
                    #pragma unroll
                    for (int kk = 0; kk < NC; kk++) {
                        float pv = *(const float*)(sm + P_OFF(buf) + kk * ROWB + v * 4);
                        atomicAdd(&sS[l * NC + kk], pv);
                        atomicAdd(&sN[l * NC + kk], pv * inv);
                    }
                }
            }
        }
        __syncthreads();

        // gather: warp w owns labels l % 16 == w; dual accumulation
        const char* pbase = sm + P_OFF(buf) + k * ROWB;
        for (int l2 = w; l2 < NL; l2 += 16) {
            int c = cursor[l2];
            int cc = c < CAP ? c : CAP;
            float ar = 0.f, an = 0.f;
            #pragma unroll
            for (int jj = 0; jj < 2; jj++) {
                int i0 = s * 4 + jj * 8;
                if (i0 < cc) {
                    ushort4 v4 = *(const ushort4*)&sidx[l2 * CAP + i0];
                    float4 n4 = *(const float4*)&sbinv[l2 * CAP + i0];
                    float p0 = *(const float*)(pbase + (int)v4.x * 4);
                    ar += p0; an += p0 * n4.x;
                    if (i0 + 1 < cc) {
                        float p1 = *(const float*)(pbase + (int)v4.y * 4);
                        ar += p1; an += p1 * n4.y;
                    }
                    if (i0 + 2 < cc) {
                        float p2 = *(const float*)(pbase + (int)v4.z * 4);
                        ar += p2; an += p2 * n4.z;
                    }
                    if (i0 + 3 < cc) {
                        float p3 = *(const float*)(pbase + (int)v4.w * 4);
                        ar += p3; an += p3 * n4.w;
                    }
                }
            }
            ar += __shfl_xor_sync(0xffffffffu, ar, 16);
            an += __shfl_xor_sync(0xffffffffu, an, 16);
            if (s == 0) {
                sS[l2 * NC + k] += ar;
                sN[l2 * NC + k] += an;
            }
            if (lane == 0) scnt[l2] += (float)c;
        }
        __syncthreads();   // protect buffer + cursor reuse
    }

    // epilogue: double-atomic reduce straight into g_red_d (staggered order)
    for (int j = tid; j < NRED; j += BLK1) {
        int i = j + blockIdx.x * 7;
        if (i >= NRED) i -= NRED * ((i) / NRED);
        int l = i / PCX, v = i % PCX;
        float r;
        if (v < NC) r = sS[l * NC + v];
        else if (v < 2 * NC) r = sN[l * NC + (v - NC)];
        else r = scnt[l];
        atomicAdd(&g_red_d[i], (double)r);
    }
}

// ---------------- Finish: means, intra, inter, loss (+ re-zero for next replay) ----------------
__global__ void k_finish(float* __restrict__ out) {
    __shared__ double shred[NRED];
    __shared__ float s_cmn[NL - 1][NC];
    int t = threadIdx.x;

    for (int i = t; i < NRED; i += blockDim.x) {
        shred[i] = g_red_d[i];
        g_red_d[i] = 0.0;          // restore state for next graph replay
    }
    __syncthreads();

    double intra_c = 0.0;
    if (t < NL) {
        float cf = fmaxf((float)shred[t * PCX + 32], 1.f);
        float m[NC];
        float n2 = 0.f;
        #pragma unroll
        for (int kk = 0; kk < NC; kk++) {
            m[kk] = (float)shred[t * PCX + kk] / cf;
            n2 += m[kk] * m[kk];
        }
        float mn = sqrtf(n2);
        if (t >= 1) {
            float inv = 1.f / fmaxf(mn, 1e-8f);
            float dot = 0.f;
            #pragma unroll
            for (int kk = 0; kk < NC; kk++) {
                s_cmn[t - 1][kk] = m[kk] * inv;
                dot += m[kk] * (float)shred[t * PCX + NC + kk];
            }
            intra_c = (double)dot / ((double)fmaxf(mn, 1e-30f) * (double)cf);
        }
    }
    __syncthreads();
    double intra = blockReduceD(intra_c);   // valid on thread 0
    __syncthreads();

    double acc = 0.0;
    for (int p = t; p < 1225; p += blockDim.x) {
        int i = 0, rem = p;
        while (rem >= (NL - 2) - i) { rem -= (NL - 2) - i; i++; }
        int j = i + 1 + rem;
        float d = 0.f;
        #pragma unroll
        for (int kk = 0; kk < NC; kk++) d += s_cmn[i][kk] * s_cmn[j][kk];
        d = fminf(fmaxf(d, 0.f), 1.f);
        acc += (double)d;
    }
    __syncthreads();
    double inter = blockReduceD(acc);       // valid on thread 0
    if (t == 0) out[0] = (float)(inter / 1225.0 - intra / (double)(NL - 1));
}

extern "C" void kernel_launch(void* const* d_in, const int* in_sizes, int n_in,
                              void* d_out, int out_size) {
    const float* pred = (const float*)d_in[0];
    const int* gt = (const int*)d_in[1];
    float* out = (float*)d_out;

    cudaFuncSetAttribute(k_fused, cudaFuncAttributeMaxDynamicSharedMemorySize, SMEM1);

    k_fused<<<GRID1, BLK1, SMEM1>>>(pred, gt);
    k_finish<<<1, 256>>>(out);
}

// round 11
// speedup vs baseline: 2.0971x; 2.0971x over previous
#include <cuda_runtime.h>
#include <math.h>

#define NL 51
#define NC 16
#define PCX 33          // 16 sums + 16 normsums + count
#define NRED (NL * PCX) // 1683
#define GRID1 296       // 2 CTAs/SM * 148
#define BLK1 512
#define TILE 512
#define NT 8192         // 4194304 voxels / 512
#define ROWB 2064       // staged p row stride (bytes): 512*4 + 16
#define CAP 32

static const long long CH_STRIDE = 1LL << 21;   // floats per channel plane

// dynamic smem layout (bytes) — same as R9 (94.1us measured)
#define P_OFF(b)   ((b) * 33024)                 // 16 rows * 2064
#define GT_OFF(b)  (66048 + (b) * 2048)
#define IDX_OFF    70144                         // ushort[51][32]
#define BINV_OFF   73408                         // float[51][32]
#define CUR_OFF    79936                         // int[51] + pad
#define SS_OFF     80144                         // float[51][16]
#define SN_OFF     83408                         // float[51][16]
#define SCNT_OFF   86672                         // float[51]
#define SMEM1      86912

#define CP_ASYNC16(dst, src) \
    asm volatile("cp.async.cg.shared.global [%0], [%1], 16;\n" :: "r"(dst), "l"(src))
#define CP_COMMIT() asm volatile("cp.async.commit_group;\n" ::: "memory")
#define CP_WAIT1()  asm volatile("cp.async.wait_group 1;\n" ::: "memory")
#define CP_WAIT0()  asm volatile("cp.async.wait_group 0;\n" ::: "memory")

// Global scratch (allocation-free rule). Zero-init at load; restored each call.
static __device__ float g_red_f[NRED];
static __device__ int   g_done;

__device__ __forceinline__ double blockReduceD(double v) {
    __shared__ double sh[32];
    int lane = threadIdx.x & 31, w = threadIdx.x >> 5;
    #pragma unroll
    for (int o = 16; o; o >>= 1) v += __shfl_down_sync(0xffffffffu, v, o);
    if (lane == 0) sh[w] = v;
    __syncthreads();
    int nw = (blockDim.x + 31) >> 5;
    v = (threadIdx.x < nw) ? sh[threadIdx.x] : 0.0;
    if (w == 0) {
        #pragma unroll
        for (int o = 16; o; o >>= 1) v += __shfl_down_sync(0xffffffffu, v, o);
    }
    return v; // valid on thread 0
}

__device__ __forceinline__ void issue_tile(unsigned sm32, int t, int buf,
                                           const float* __restrict__ pred,
                                           const int* __restrict__ gt) {
    size_t v0 = (size_t)t * TILE;
    const char* psrc = (const char*)(pred + (v0 >> 21) * (NC * (size_t)CH_STRIDE)
                                          + (v0 & (size_t)(CH_STRIDE - 1)));
    int tid = threadIdx.x;
    #pragma unroll
    for (int it = 0; it < 4; it++) {
        int o = tid + it * BLK1;         // 0..2047
        int k = o >> 7, c = o & 127;     // 128 16B-granules per 512-float row
        unsigned dst = sm32 + P_OFF(buf) + k * ROWB + c * 16;
        const char* src = psrc + (size_t)k * ((size_t)CH_STRIDE * 4) + (size_t)c * 16;
        CP_ASYNC16(dst, src);
    }
    if (tid < 128) {
        unsigned dstg = sm32 + GT_OFF(buf) + tid * 16;
        const char* srcg = (const char*)(gt + v0) + (size_t)tid * 16;
        CP_ASYNC16(dstg, srcg);
    }
}

// ---------- Fused: count, sum(p), sum(p/|p|) per label in ONE read + inline finish ----------
__global__ void __launch_bounds__(BLK1, 2) k_fused(const float* __restrict__ pred,
                                                   const int* __restrict__ gt,
                                                   float* __restrict__ out) {
    extern __shared__ char sm[];
    float* sS = (float*)(sm + SS_OFF);
    float* sN = (float*)(sm + SN_OFF);
    float* scnt = (float*)(sm + SCNT_OFF);
    int* cursor = (int*)(sm + CUR_OFF);
    unsigned short* sidx = (unsigned short*)(sm + IDX_OFF);
    float* sbinv = (float*)(sm + BINV_OFF);
    const int tid = threadIdx.x;
    const int lane = tid & 31, w = tid >> 5;
    const int k = lane & 15, s = lane >> 4;

    unsigned sm32;
    asm("{ .reg .u64 t; cvta.to.shared.u64 t, %1; cvt.u32.u64 %0, t; }"
        : "=r"(sm32) : "l"(sm));

    for (int i = tid; i < NL * NC; i += BLK1) { sS[i] = 0.f; sN[i] = 0.f; }
    if (tid < NL) { scnt[tid] = 0.f; cursor[tid] = 0; }
    __syncthreads();

    issue_tile(sm32, blockIdx.x, 0, pred, gt);
    CP_COMMIT();

    int it = 0;
    for (int t = blockIdx.x; t < NT; t += GRID1, it++) {
        int buf = it & 1;
        int tn = t + GRID1;
        // B_a: all warps finished previous gather (safe to overwrite buf^1) and
        // previous cursor clears are visible.
        __syncthreads();
        if (tn < NT) {
            issue_tile(sm32, tn, buf ^ 1, pred, gt);
            CP_COMMIT();
            CP_WAIT1();
        } else {
            CP_WAIT0();
        }
        // B_b: everyone's cp.async waits passed -> tile buf fully visible
        __syncthreads();

        // scatter + norm: 1 voxel/thread; inv-norm stays in registers
        {
            int l = *(const int*)(sm + GT_OFF(buf) + tid * 4);
            const char* pb = sm + P_OFF(buf) + tid * 4;
            float q = 0.f;
            #pragma unroll
            for (int kk = 0; kk < NC; kk++) {
                float pp = *(const float*)(pb + kk * ROWB);
                q += pp * pp;
            }
            float inv = rsqrtf(fmaxf(q, 1e-30f));
            int r = atomicAdd(&cursor[l], 1);
            if (r < CAP) {
                sidx[l * CAP + r] = (unsigned short)tid;
                sbinv[l * CAP + r] = inv;
            } else {
                #pragma unroll
                for (int kk = 0; kk < NC; kk++) {
                    float pv = *(const float*)(sm + P_OFF(buf) + kk * ROWB + tid * 4);
                    atomicAdd(&sS[l * NC + kk], pv);
                    atomicAdd(&sN[l * NC + kk], pv * inv);
                }
            }
        }
        // B_c: bins complete
        __syncthreads();

        // gather: warp w owns labels l % 16 == w; dual accumulation, ILP-4;
        // owner clears its cursor (visible to next scatter via B_a+B_b).
        const char* pbase = sm + P_OFF(buf) + k * ROWB;
        for (int l2 = w; l2 < NL; l2 += 16) {
            int c = cursor[l2];
            __syncwarp();
            if (lane == 0) { cursor[l2] = 0; scnt[l2] += (float)c; }
            int cc = c < CAP ? c : CAP;
            float ar = 0.f, an = 0.f;
            #pragma unroll
            for (int jj = 0; jj < 4; jj++) {
                int i0 = s * 4 + jj * 8;
                if (i0 < cc) {
                    ushort4 v4 = *(const ushort4*)&sidx[l2 * CAP + i0];
                    float4 n4 = *(const float4*)&sbinv[l2 * CAP + i0];
                    float p0 = *(const float*)(pbase + (int)v4.x * 4);
                    ar += p0; an += p0 * n4.x;
                    if (i0 + 1 < cc) {
                        float p1 = *(const float*)(pbase + (int)v4.y * 4);
                        ar += p1; an += p1 * n4.y;
                    }
                    if (i0 + 2 < cc) {
                        float p2 = *(const float*)(pbase + (int)v4.z * 4);
                        ar += p2; an += p2 * n4.z;
                    }
                    if (i0 + 3 < cc) {
                        float p3 = *(const float*)(pbase + (int)v4.w * 4);
                        ar += p3; an += p3 * n4.w;
                    }
                }
            }
            ar += __shfl_xor_sync(0xffffffffu, ar, 16);
            an += __shfl_xor_sync(0xffffffffu, an, 16);
            if (s == 0) {
                sS[l2 * NC + k] += ar;
                sN[l2 * NC + k] += an;
            }
        }
    }
    __syncthreads();

    // epilogue: f32 atomic reduce into g_red_f (spread/staggered addresses)
    for (int j = tid; j < NRED; j += BLK1) {
        int i = j + blockIdx.x * 53;
        i = i % NRED;
        int l = i / PCX, v = i % PCX;
        float r;
        if (v < NC) r = sS[l * NC + v];
        else if (v < 2 * NC) r = sN[l * NC + (v - NC)];
        else r = scnt[l];
        atomicAdd(&g_red_f[i], r);
    }

    // last-CTA inline finish
    __shared__ int s_ticket;
    __threadfence();
    __syncthreads();
    if (tid == 0) s_ticket = atomicAdd(&g_done, 1);
    __syncthreads();
    if (s_ticket != GRID1 - 1) return;
    __threadfence();

    // reuse smem: s_red (f32 copies), s_cmn
    float* s_red = (float*)(sm);                 // NRED floats
    float* s_cmn2 = (float*)(sm + 8192);         // (NL-1)*NC floats
    for (int i = tid; i < NRED; i += BLK1) {
        s_red[i] = g_red_f[i];
        g_red_f[i] = 0.f;                        // restore for next graph replay
    }
    if (tid == 0) g_done = 0;
    __syncthreads();

    double intra_c = 0.0;
    if (tid < NL) {
        float cf = fmaxf(s_red[tid * PCX + 32], 1.f);
        float m[NC];
        float n2 = 0.f;
        #pragma unroll
        for (int kk = 0; kk < NC; kk++) {
            m[kk] = s_red[tid * PCX + kk] / cf;
            n2 += m[kk] * m[kk];
        }
        float mn = sqrtf(n2);
        if (tid >= 1) {
            float inv = 1.f / fmaxf(mn, 1e-8f);
            float dot = 0.f;
            #pragma unroll
            for (int kk = 0; kk < NC; kk++) {
                s_cmn2[(tid - 1) * NC + kk] = m[kk] * inv;
                dot += m[kk] * s_red[tid * PCX + NC + kk];
            }
            intra_c = (double)dot / ((double)fmaxf(mn, 1e-30f) * (double)cf);
        }
    }
    __syncthreads();
    double intra = blockReduceD(intra_c);
    __syncthreads();

    double acc = 0.0;
    for (int p = tid; p < 1225; p += BLK1) {
        int i = 0, rem = p;
        while (rem >= (NL - 2) - i) { rem -= (NL - 2) - i; i++; }
        int j = i + 1 + rem;
        float d = 0.f;
        #pragma unroll
        for (int kk = 0; kk < NC; kk++) d += s_cmn2[i * NC + kk] * s_cmn2[j * NC + kk];
        d = fminf(fmaxf(d, 0.f), 1.f);
        acc += (double)d;
    }
    __syncthreads();
    double inter = blockReduceD(acc);
    if (tid == 0) out[0] = (float)(inter / 1225.0 - intra / (double)(NL - 1));
}

extern "C" void kernel_launch(void* const* d_in, const int* in_sizes, int n_in,
                              void* d_out, int out_size) {
    const float* pred = (const float*)d_in[0];
    const int* gt = (const int*)d_in[1];
    float* out = (float*)d_out;

    cudaFuncSetAttribute(k_fused, cudaFuncAttributeMaxDynamicSharedMemorySize, SMEM1);
    k_fused<<<GRID1, BLK1, SMEM1>>>(pred, gt, out);
}